// round 5
// baseline (speedup 1.0000x reference)
#include <cuda_runtime.h>
#include <cuda_bf16.h>
#include <math.h>

#define BB 8
#define TT 256
#define UU 65
#define UL 64
#define VV 1024
#define NEG_BIG (-1e30f)

__device__ float g_lp_blank[BB * TT * UU];
__device__ float g_lp_label[BB * TT * UL];
__device__ int   g_cnt[BB * TT];          // rows published per (b,t); cleared by finalize
__device__ float g_ll[BB];

__device__ __forceinline__ float warpMax(float v) {
#pragma unroll
    for (int o = 16; o > 0; o >>= 1) v = fmaxf(v, __shfl_xor_sync(0xffffffffu, v, o));
    return v;
}
__device__ __forceinline__ float warpSum(float v) {
#pragma unroll
    for (int o = 16; o > 0; o >>= 1) v += __shfl_xor_sync(0xffffffffu, v, o);
    return v;
}
__device__ __forceinline__ float lae(float a, float b) {
    float m = fmaxf(a, b);
    float d = fminf(a, b) - m;
    return m + __logf(1.f + __expf(d));
}

// ---------------- fused kernel: lse producers + alpha consumers --------------
__global__ void __launch_bounds__(256) rnnt_fused_kernel(const float* __restrict__ acts,
                                                         const int* __restrict__ labels,
                                                         const int* __restrict__ act_lens,
                                                         const int* __restrict__ label_lens) {
    const int lane = threadIdx.x & 31;
    const int wid  = threadIdx.x >> 5;

    if (blockIdx.x >= 8) {
        // ================= LSE producer: warp-per-row, t-major order =========
        const int sched = (blockIdx.x - 8) * 8 + wid;          // 0 .. 133119
        const int t   = sched / (BB * UU);
        const int rem = sched - t * (BB * UU);
        const int b   = rem / UU;
        const int u   = rem - b * UU;
        const int row = (b * TT + t) * UU + u;

        const float4* a4 = reinterpret_cast<const float4*>(acts + (size_t)row * VV);
        float4 v[8];
#pragma unroll
        for (int j = 0; j < 8; ++j) v[j] = a4[lane + 32 * j];

        float m = -INFINITY;
#pragma unroll
        for (int j = 0; j < 8; ++j)
            m = fmaxf(m, fmaxf(fmaxf(v[j].x, v[j].y), fmaxf(v[j].z, v[j].w)));
        m = warpMax(m);

        float s = 0.f;
#pragma unroll
        for (int j = 0; j < 8; ++j)
            s += __expf(v[j].x - m) + __expf(v[j].y - m) + __expf(v[j].z - m) + __expf(v[j].w - m);
        s = warpSum(s);
        const float lse = m + __logf(s);

        float lv = 0.f;
        if (u < UL) {
            const int lab = labels[b * UL + u];
            const int q = lab >> 2, c = lab & 3, jj = q >> 5;
            float cand = 0.f;
#pragma unroll
            for (int j = 0; j < 8; ++j) {
                if (j == jj) {
                    float4 f = v[j];
                    cand = (c == 0) ? f.x : (c == 1) ? f.y : (c == 2) ? f.z : f.w;
                }
            }
            lv = __shfl_sync(0xffffffffu, cand, q & 31);
        }
        if (lane == 0) {
            g_lp_blank[row] = v[0].x - lse;
            if (u < UL) g_lp_label[(b * TT + t) * UL + u] = lv - lse;
            __threadfence();                       // release lp stores
            atomicAdd(&g_cnt[b * TT + t], 1);      // publish
        }
        return;
    }

    // ================= ALPHA consumer: one warp per batch ====================
    if (wid != 0) return;
    const int b = blockIdx.x;

    const int t_tgt = act_lens[b] - 1;
    const int u_tgt = label_lens[b];
    const int d_tgt = t_tgt + u_tgt;

    const float* lpb = g_lp_blank + (size_t)b * TT * UU;
    const float* lpl = g_lp_label + (size_t)b * TT * UL;
    const volatile int* cnt = g_cnt + b * TT;

    const int u0 = 2 * lane, u1 = u0 + 1;
    const int ul0 = (lane == 0) ? 0 : (u0 - 1);
    float a0 = 0.f, a1 = 0.f, a2 = 0.f;
    float tgt = 0.f;

#pragma unroll 1
    for (int d = 1; d < TT + UU - 1; ++d) {
        // gate: diagonal d touches t-rows up to min(d, TT-1)
        if (d <= TT - 1) {
            if (cnt[d] < UU) {
                while (cnt[d] < UU) __nanosleep(128);
            }
            __threadfence();                       // acquire before lp reads
        }
        __syncwarp();

        float pm = __shfl_up_sync(0xffffffffu, a1, 1);
        pm = (lane == 0) ? NEG_BIG : pm;

        const int t0 = d - u0, t1 = t0 - 1, t2 = d - 64;

        // cell 0: u = u0
        const int tb0 = min(max(t0 - 1, 0), TT - 1);
        const int tl0 = min(max(t0,     0), TT - 1);
        float bl0 = lpb[tb0 * UU + u0];
        float lb0 = lpl[tl0 * UL + ul0];
        bl0 = (t0 >= 1) ? bl0 : NEG_BIG;
        const float n0 = lae(a0 + bl0, pm + lb0);

        // cell 1: u = u1
        const int tb1 = min(max(t1 - 1, 0), TT - 1);
        const int tl1 = min(max(t1,     0), TT - 1);
        float bl1 = lpb[tb1 * UU + u1];
        float lb1 = lpl[tl1 * UL + u0];
        bl1 = (t1 >= 1) ? bl1 : NEG_BIG;
        const float n1 = lae(a1 + bl1, a0 + lb1);

        // cell 2: u = 64 (uniform addresses; meaningful in lane 31 only)
        const int tb2 = min(max(t2 - 1, 0), TT - 1);
        const int tl2 = min(max(t2,     0), TT - 1);
        float bl2 = lpb[tb2 * UU + 64];
        float lb2 = lpl[tl2 * UL + 63];
        bl2 = (t2 >= 1) ? bl2 : NEG_BIG;
        const float n2 = lae(a2 + bl2, a1 + lb2);

        a0 = (t0 >= 0 && t0 < TT) ? n0 : a0;
        a1 = (t1 >= 0 && t1 < TT) ? n1 : a1;
        a2 = (t2 >= 0 && t2 < TT) ? n2 : a2;

        const float pick = (u_tgt == u0) ? n0 : ((u_tgt == u1) ? n1 : n2);
        tgt = (d == d_tgt) ? pick : tgt;
    }

    const int owner = (u_tgt >= 64) ? 31 : (u_tgt >> 1);
    const float av = __shfl_sync(0xffffffffu, tgt, owner);
    if (lane == 0) g_ll[b] = av + lpb[t_tgt * UU + u_tgt];
}

// ---------------- finalize: output + reset publish counters ------------------
__global__ void __launch_bounds__(256) finalize_kernel(float* __restrict__ out) {
    const int tid = threadIdx.x;
    for (int i = tid; i < BB * TT; i += 256) g_cnt[i] = 0;   // clean for next replay
    if (tid == 0) {
        float s = 0.f;
#pragma unroll
        for (int i = 0; i < BB; ++i) s += g_ll[i];
        out[0] = -s / (float)BB;
    }
}

extern "C" void kernel_launch(void* const* d_in, const int* in_sizes, int n_in,
                              void* d_out, int out_size) {
    const float* acts       = (const float*)d_in[0];
    const int*   labels     = (const int*)d_in[1];
    const int*   act_lens   = (const int*)d_in[2];
    const int*   label_lens = (const int*)d_in[3];
    float* out = (float*)d_out;

    const int lse_blocks = (BB * TT * UU) / 8;     // 16640
    rnnt_fused_kernel<<<8 + lse_blocks, 256>>>(acts, labels, act_lens, label_lens);
    finalize_kernel<<<1, 256>>>(out);
}

// round 6
// speedup vs baseline: 3.4507x; 3.4507x over previous
#include <cuda_runtime.h>
#include <cuda_bf16.h>
#include <math.h>

#define BB 8
#define TT 256
#define UU 65
#define UL 64
#define VV 1024
#define SB 66            // padded smem row stride: 2-way max bank conflict on diagonals
#define NEG_BIG (-1e30f)
#define LOG2E 1.4426950408889634f
#define LN2F  0.6931471805599453f

__device__ float g_lp_blank[BB * TT * UU];
__device__ float g_lp_label[BB * TT * UL];
__device__ float g_ll[BB];
__device__ int   g_done;

__device__ __forceinline__ float warpMax(float v) {
#pragma unroll
    for (int o = 16; o > 0; o >>= 1) v = fmaxf(v, __shfl_xor_sync(0xffffffffu, v, o));
    return v;
}
__device__ __forceinline__ float warpSum(float v) {
#pragma unroll
    for (int o = 16; o > 0; o >>= 1) v += __shfl_xor_sync(0xffffffffu, v, o);
    return v;
}

// ---------------- Kernel 1: warp-per-row logsumexp (proven 77-85% DRAM) -----
__global__ void __launch_bounds__(256) lse_kernel(const float* __restrict__ acts,
                                                  const int* __restrict__ labels) {
    const int row  = blockIdx.x * 8 + (threadIdx.x >> 5);
    const int lane = threadIdx.x & 31;

    const int u  = row % UU;
    const int bt = row / UU;
    const int b  = bt / TT;

    const float4* a4 = reinterpret_cast<const float4*>(acts + (size_t)row * VV);
    float4 v[8];
#pragma unroll
    for (int j = 0; j < 8; ++j) v[j] = a4[lane + 32 * j];

    float m = -INFINITY;
#pragma unroll
    for (int j = 0; j < 8; ++j)
        m = fmaxf(m, fmaxf(fmaxf(v[j].x, v[j].y), fmaxf(v[j].z, v[j].w)));
    m = warpMax(m);

    float s = 0.f;
#pragma unroll
    for (int j = 0; j < 8; ++j)
        s += __expf(v[j].x - m) + __expf(v[j].y - m) + __expf(v[j].z - m) + __expf(v[j].w - m);
    s = warpSum(s);
    const float lse = m + __logf(s);

    if (u < UL) {
        const int lab = labels[b * UL + u];
        const int q = lab >> 2, c = lab & 3, jj = q >> 5;
        float cand = 0.f;
#pragma unroll
        for (int j = 0; j < 8; ++j) {
            if (j == jj) {
                float4 f = v[j];
                cand = (c == 0) ? f.x : (c == 1) ? f.y : (c == 2) ? f.z : f.w;
            }
        }
        const float lv = __shfl_sync(0xffffffffu, cand, q & 31);
        if (lane == 0) g_lp_label[bt * UL + u] = lv - lse;
    }
    if (lane == 0) g_lp_blank[row] = v[0].x - lse;
}

// log-add-exp in log2 domain: no FMULs, just fmax/fmin/sub/ex2/add/lg2/add.
__device__ __forceinline__ float lae2(float a, float b) {
    float m = fmaxf(a, b);
    float d = fminf(a, b) - m;
    float p, r;
    asm("ex2.approx.ftz.f32 %0, %1;" : "=f"(p) : "f"(d));
    float q = 1.f + p;
    asm("lg2.approx.ftz.f32 %0, %1;" : "=f"(r) : "f"(q));
    return m + r;
}

// ---------------- Kernel 2: single-warp wavefront DP, 3-phase loop ----------
__global__ void __launch_bounds__(1024) alpha_kernel(const int* __restrict__ act_lens,
                                                     const int* __restrict__ label_lens,
                                                     float* __restrict__ out) {
    extern __shared__ float sm[];
    float* s_blank = sm;                 // TT * SB, cols 0..64, scaled by log2(e)
    float* s_label = sm + TT * SB;       // TT * SB, cols 0..63, scaled by log2(e)

    const int b    = blockIdx.x;
    const int tid  = threadIdx.x;
    const int lane = tid & 31;
    const int wid  = tid >> 5;

    for (int t = wid; t < TT; t += 32) {
        const float* gb = g_lp_blank + ((size_t)b * TT + t) * UU;
        const float* gl = g_lp_label + ((size_t)b * TT + t) * UL;
        s_blank[t * SB + lane]      = gb[lane]      * LOG2E;
        s_blank[t * SB + 32 + lane] = gb[32 + lane] * LOG2E;
        if (lane == 0) s_blank[t * SB + 64] = gb[64] * LOG2E;
        s_label[t * SB + lane]      = gl[lane]      * LOG2E;
        s_label[t * SB + 32 + lane] = gl[32 + lane] * LOG2E;
    }
    __syncthreads();
    if (wid != 0) return;

    const int t_tgt = act_lens[b] - 1;
    const int u_tgt = label_lens[b];
    const int d_tgt = t_tgt + u_tgt;

    const int u0 = 2 * lane, u1 = u0 + 1;
    const int ul0 = (lane == 0) ? 0 : (u0 - 1);
    float a0 = 0.f, a1 = 0.f, a2 = 0.f;    // alpha[u0], alpha[u1], alpha[64]
    float tgt = 0.f;

    // checked diagonal (boundary phases)
    auto checked = [&](int d) {
        float pm = __shfl_up_sync(0xffffffffu, a1, 1);
        pm = (lane == 0) ? NEG_BIG : pm;

        const int t0 = d - u0, t1 = t0 - 1, t2 = d - 64;

        const int tb0 = min(max(t0 - 1, 0), TT - 1);
        const int tl0 = min(max(t0,     0), TT - 1);
        float bl0 = s_blank[tb0 * SB + u0];
        float lb0 = s_label[tl0 * SB + ul0];
        bl0 = (t0 >= 1) ? bl0 : NEG_BIG;
        const float n0 = lae2(a0 + bl0, pm + lb0);

        const int tb1 = min(max(t1 - 1, 0), TT - 1);
        const int tl1 = min(max(t1,     0), TT - 1);
        float bl1 = s_blank[tb1 * SB + u1];
        float lb1 = s_label[tl1 * SB + u0];
        bl1 = (t1 >= 1) ? bl1 : NEG_BIG;
        const float n1 = lae2(a1 + bl1, a0 + lb1);

        const int tb2 = min(max(t2 - 1, 0), TT - 1);
        const int tl2 = min(max(t2,     0), TT - 1);
        float bl2 = s_blank[tb2 * SB + 64];
        float lb2 = s_label[tl2 * SB + 63];
        bl2 = (t2 >= 1) ? bl2 : NEG_BIG;
        const float n2 = lae2(a2 + bl2, a1 + lb2);

        a0 = (t0 >= 0 && t0 < TT) ? n0 : a0;
        a1 = (t1 >= 0 && t1 < TT) ? n1 : a1;
        a2 = (t2 >= 0 && t2 < TT) ? n2 : a2;

        const float pick = (u_tgt == u0) ? n0 : ((u_tgt == u1) ? n1 : n2);
        tgt = (d == d_tgt) ? pick : tgt;
    };

    // Phase A: d = 1..64 (boundaries)
#pragma unroll 1
    for (int d = 1; d <= 64; ++d) checked(d);

    // Phase B: d = 65..255 — all cells interior: no clamps, no commit selects,
    // pointer-increment addressing.
    {
        float* pb0 = s_blank + (64 - u0) * SB + u0;   // blank[t0-1, u0]
        float* pl0 = s_label + (65 - u0) * SB + ul0;  // label[t0,   u0-1]
        float* pb1 = s_blank + (63 - u0) * SB + u1;   // blank[t1-1, u1]
        float* pl1 = s_label + (64 - u0) * SB + u0;   // label[t1,   u0]
        float* pb2 = s_blank + 64;                    // blank[t2-1, 64]
        float* pl2 = s_label + SB + 63;               // label[t2,   63]

#pragma unroll 2
        for (int d = 65; d <= 255; ++d) {
            float pm = __shfl_up_sync(0xffffffffu, a1, 1);
            pm = (lane == 0) ? NEG_BIG : pm;

            const float n0 = lae2(a0 + pb0[0], pm + pl0[0]);
            const float n1 = lae2(a1 + pb1[0], a0 + pl1[0]);
            const float n2 = lae2(a2 + pb2[0], a1 + pl2[0]);

            const float pick = (u_tgt == u0) ? n0 : ((u_tgt == u1) ? n1 : n2);
            tgt = (d == d_tgt) ? pick : tgt;

            a0 = n0; a1 = n1; a2 = n2;
            pb0 += SB; pl0 += SB; pb1 += SB; pl1 += SB; pb2 += SB; pl2 += SB;
        }
    }

    // Phase C: d = 256..319 (boundaries)
#pragma unroll 1
    for (int d = 256; d <= TT + UU - 2; ++d) checked(d);

    const int owner = (u_tgt >= 64) ? 31 : (u_tgt >> 1);
    const float av = __shfl_sync(0xffffffffu, tgt, owner);
    if (lane == 0) {
        g_ll[b] = (av + s_blank[t_tgt * SB + u_tgt]) * LN2F;   // back to ln domain
        __threadfence();
        const int old = atomicAdd(&g_done, 1);
        if (old == BB - 1) {                    // last CTA: deterministic finalize
            float s = 0.f;
#pragma unroll
            for (int i = 0; i < BB; ++i) s += g_ll[i];
            out[0] = -s / (float)BB;
            g_done = 0;                         // reset for next graph replay
            __threadfence();
        }
    }
}

extern "C" void kernel_launch(void* const* d_in, const int* in_sizes, int n_in,
                              void* d_out, int out_size) {
    const float* acts       = (const float*)d_in[0];
    const int*   labels     = (const int*)d_in[1];
    const int*   act_lens   = (const int*)d_in[2];
    const int*   label_lens = (const int*)d_in[3];
    float* out = (float*)d_out;

    const int smem_alpha = 2 * TT * SB * (int)sizeof(float);
    cudaFuncSetAttribute(alpha_kernel, cudaFuncAttributeMaxDynamicSharedMemorySize, smem_alpha);

    const int rows = BB * TT * UU;                 // 133120 = 8 warps * 16640 blocks
    lse_kernel<<<rows / 8, 256>>>(acts, labels);
    alpha_kernel<<<BB, 1024, smem_alpha>>>(act_lens, label_lens, out);
}